// round 6
// baseline (speedup 1.0000x reference)
#include <cuda_runtime.h>
#include <math.h>
#include <stdint.h>

#define BB   2
#define NN   768
#define TT   96
#define FMF  8
#define HIDD 64
#define TDD  32

#define NTILE 24           // 768/32
#define NUPPER 300         // 24*25/2
#define TOTTILES (NUPPER * BB)
#define GRIDP 592          // 148 SMs * 2 CTAs, one wave slot count
#define PAD 68             // word-pad so (4*row + col) & 31 is lane-unique

// ---------------------------------------------------------------------------
// helpers
// ---------------------------------------------------------------------------
__device__ __forceinline__ uint32_t f2tf32(float f) {
    uint32_t r; asm("cvt.rna.tf32.f32 %0, %1;" : "=r"(r) : "f"(f)); return r;
}

__device__ __forceinline__ void mma_tf32(float* d,
                                         uint32_t a0, uint32_t a1, uint32_t a2, uint32_t a3,
                                         uint32_t b0, uint32_t b1) {
    asm volatile(
        "mma.sync.aligned.m16n8k8.row.col.f32.tf32.tf32.f32 "
        "{%0,%1,%2,%3}, {%4,%5,%6,%7}, {%8,%9}, {%0,%1,%2,%3};"
        : "+f"(d[0]), "+f"(d[1]), "+f"(d[2]), "+f"(d[3])
        : "r"(a0), "r"(a1), "r"(a2), "r"(a3), "r"(b0), "r"(b1));
}

// Scratch (allocation-free rule: __device__ globals)
__device__ float g_h[BB * NN * HIDD];
__device__ float g_P[BB * NN * HIDD];   // h @ w_i + ps_b1
__device__ float g_Q[BB * NN * HIDD];   // h @ w_j

// ---------------------------------------------------------------------------
// Kernel 1: per-node features. TWO nodes per warp (shared weight loads,
// doubled ILP/MLP); 64-thread blocks for even SM spread. Shuffle-only.
// ---------------------------------------------------------------------------
__global__ __launch_bounds__(64)
void node_kernel(const float* __restrict__ x_hist, const float* __restrict__ x_mark,
                 const float* __restrict__ te_w1, const float* __restrict__ te_b1,
                 const float* __restrict__ te_w2, const float* __restrict__ te_b2,
                 const float* __restrict__ me_w1, const float* __restrict__ me_b1,
                 const float* __restrict__ me_w2, const float* __restrict__ me_b2,
                 const float* __restrict__ nf_w,  const float* __restrict__ nf_b,
                 const float* __restrict__ ps_w1, const float* __restrict__ ps_b1)
{
    const int lane = threadIdx.x & 31;
    const int nodeA = blockIdx.x * 4 + (threadIdx.x >> 5) * 2;
    const int nodeB = nodeA + 1;

    const float* xhA = x_hist + (size_t)nodeA * TT;
    const float* xhB = x_hist + (size_t)nodeB * TT;
    const float* xmA = x_mark + (size_t)nodeA * TT * FMF;
    const float* xmB = x_mark + (size_t)nodeB * TT * FMF;

    // ---- stats over T = 96 = 3*32 (both nodes interleaved) ----
    float a0 = xhA[lane], a1 = xhA[lane + 32], a2 = xhA[lane + 64];
    float b0 = xhB[lane], b1 = xhB[lane + 32], b2 = xhB[lane + 64];
    float sA = a0 + a1 + a2,  mA = fmaxf(a0, fmaxf(a1, a2));
    float sB = b0 + b1 + b2,  mB = fmaxf(b0, fmaxf(b1, b2));
    #pragma unroll
    for (int off = 16; off > 0; off >>= 1) {
        sA += __shfl_xor_sync(0xFFFFFFFF, sA, off);
        mA  = fmaxf(mA, __shfl_xor_sync(0xFFFFFFFF, mA, off));
        sB += __shfl_xor_sync(0xFFFFFFFF, sB, off);
        mB  = fmaxf(mB, __shfl_xor_sync(0xFFFFFFFF, mB, off));
    }
    const float stA0 = __shfl_sync(0xFFFFFFFF, a2, 31);
    const float stB0 = __shfl_sync(0xFFFFFFFF, b2, 31);
    const float stA1 = sA * (1.f / (float)TT), stB1 = sB * (1.f / (float)TT);
    const float stA2 = mA, stB2 = mB;

    // ---- mark mean: 768 = 32*24 coalesced; lane l accumulates feature l&7 ----
    float msA = 0.f, msB = 0.f;
    #pragma unroll
    for (int q = 0; q < 24; q++) { msA += xmA[lane + 32 * q]; msB += xmB[lane + 32 * q]; }
    msA += __shfl_xor_sync(0xFFFFFFFF, msA, 8);
    msA += __shfl_xor_sync(0xFFFFFFFF, msA, 16);
    msB += __shfl_xor_sync(0xFFFFFFFF, msB, 8);
    msB += __shfl_xor_sync(0xFFFFFFFF, msB, 16);
    msA *= (1.f / (float)TT); msB *= (1.f / (float)TT);

    // ---- layer 1 (weights loaded once, used for both nodes) ----
    const float w10 = te_w1[lane], w11 = te_w1[32 + lane], w12 = te_w1[64 + lane];
    const float tb1 = te_b1[lane];
    float t1A = fmaxf(fmaf(stA2, w12, fmaf(stA1, w11, fmaf(stA0, w10, tb1))), 0.f);
    float t1B = fmaxf(fmaf(stB2, w12, fmaf(stB1, w11, fmaf(stB0, w10, tb1))), 0.f);

    const float mb1 = me_b1[lane];
    float m1A = mb1, m1B = mb1;
    #pragma unroll
    for (int c = 0; c < FMF; c++) {
        const float wv = me_w1[c * TDD + lane];
        m1A = fmaf(__shfl_sync(0xFFFFFFFF, msA, c), wv, m1A);
        m1B = fmaf(__shfl_sync(0xFFFFFFFF, msB, c), wv, m1B);
    }
    m1A = fmaxf(m1A, 0.f); m1B = fmaxf(m1B, 0.f);

    // ---- layer 2 ----
    float t2A = te_b2[lane], m2A = me_b2[lane];
    float t2B = t2A, m2B = m2A;
    #pragma unroll
    for (int c = 0; c < TDD; c++) {
        const float wt = te_w2[c * TDD + lane];
        const float wm = me_w2[c * TDD + lane];
        t2A = fmaf(__shfl_sync(0xFFFFFFFF, t1A, c), wt, t2A);
        t2B = fmaf(__shfl_sync(0xFFFFFFFF, t1B, c), wt, t2B);
        m2A = fmaf(__shfl_sync(0xFFFFFFFF, m1A, c), wm, m2A);
        m2B = fmaf(__shfl_sync(0xFFFFFFFF, m1B, c), wm, m2B);
    }

    // ---- node fuse: h[2*lane], h[2*lane+1] per node ----
    const int k0 = 2 * lane;
    const float2 hb = *(const float2*)&nf_b[k0];
    float hA0 = hb.x, hA1 = hb.y, hB0 = hb.x, hB1 = hb.y;
    #pragma unroll
    for (int c = 0; c < TDD; c++) {
        const float2 wv = *(const float2*)&nf_w[c * HIDD + k0];
        const float ca = __shfl_sync(0xFFFFFFFF, t2A, c);
        const float cb = __shfl_sync(0xFFFFFFFF, t2B, c);
        hA0 = fmaf(ca, wv.x, hA0); hA1 = fmaf(ca, wv.y, hA1);
        hB0 = fmaf(cb, wv.x, hB0); hB1 = fmaf(cb, wv.y, hB1);
    }
    #pragma unroll
    for (int c = 0; c < TDD; c++) {
        const float2 wv = *(const float2*)&nf_w[(TDD + c) * HIDD + k0];
        const float ca = __shfl_sync(0xFFFFFFFF, m2A, c);
        const float cb = __shfl_sync(0xFFFFFFFF, m2B, c);
        hA0 = fmaf(ca, wv.x, hA0); hA1 = fmaf(ca, wv.y, hA1);
        hB0 = fmaf(cb, wv.x, hB0); hB1 = fmaf(cb, wv.y, hB1);
    }
    hA0 = fmaxf(hA0, 0.f); hA1 = fmaxf(hA1, 0.f);
    hB0 = fmaxf(hB0, 0.f); hB1 = fmaxf(hB1, 0.f);
    *(float2*)&g_h[(size_t)nodeA * HIDD + k0] = make_float2(hA0, hA1);
    *(float2*)&g_h[(size_t)nodeB * HIDD + k0] = make_float2(hB0, hB1);

    // ---- P = h@w_i + ps_b1, Q = h@w_j (weights shared across nodes) ----
    const float2 pb = *(const float2*)&ps_b1[k0];
    float pA0 = pb.x, pA1 = pb.y, qA0 = 0.f, qA1 = 0.f;
    float pB0 = pb.x, pB1 = pb.y, qB0 = 0.f, qB1 = 0.f;
    #pragma unroll
    for (int cc = 0; cc < TDD; cc++) {
        const float2 wiA = *(const float2*)&ps_w1[(2 * cc) * HIDD + k0];
        const float2 wiB = *(const float2*)&ps_w1[(2 * cc + 1) * HIDD + k0];
        const float2 wjA = *(const float2*)&ps_w1[(HIDD + 2 * cc) * HIDD + k0];
        const float2 wjB = *(const float2*)&ps_w1[(HIDD + 2 * cc + 1) * HIDD + k0];
        const float haA = __shfl_sync(0xFFFFFFFF, hA0, cc);
        const float hbA = __shfl_sync(0xFFFFFFFF, hA1, cc);
        const float haB = __shfl_sync(0xFFFFFFFF, hB0, cc);
        const float hbB = __shfl_sync(0xFFFFFFFF, hB1, cc);
        pA0 = fmaf(haA, wiA.x, pA0); pA1 = fmaf(haA, wiA.y, pA1);
        pA0 = fmaf(hbA, wiB.x, pA0); pA1 = fmaf(hbA, wiB.y, pA1);
        qA0 = fmaf(haA, wjA.x, qA0); qA1 = fmaf(haA, wjA.y, qA1);
        qA0 = fmaf(hbA, wjB.x, qA0); qA1 = fmaf(hbA, wjB.y, qA1);
        pB0 = fmaf(haB, wiA.x, pB0); pB1 = fmaf(haB, wiA.y, pB1);
        pB0 = fmaf(hbB, wiB.x, pB0); pB1 = fmaf(hbB, wiB.y, pB1);
        qB0 = fmaf(haB, wjA.x, qB0); qB1 = fmaf(haB, wjA.y, qB1);
        qB0 = fmaf(hbB, wjB.x, qB0); qB1 = fmaf(hbB, wjB.y, qB1);
    }
    *(float2*)&g_P[(size_t)nodeA * HIDD + k0] = make_float2(pA0, pA1);
    *(float2*)&g_Q[(size_t)nodeA * HIDD + k0] = make_float2(qA0, qA1);
    *(float2*)&g_P[(size_t)nodeB * HIDD + k0] = make_float2(pB0, pB1);
    *(float2*)&g_Q[(size_t)nodeB * HIDD + k0] = make_float2(qB0, qB1);
}

// ---------------------------------------------------------------------------
// Kernel 2: pairwise delta via tf32 mma.sync. Persistent grid of 592 blocks
// (one 2-CTA/SM wave); blocks stride over 600 tiles. B table loaded once.
// ---------------------------------------------------------------------------
#define BF_BYTES (8 * 4 * 32 * 16)                   // uint4 table, 16 KB
#define SM_BYTES (BF_BYTES + (6 * 32 * PAD + 64) * 4)

__global__ __launch_bounds__(256, 2)
void pair_kernel(const float* __restrict__ ps_w1, const float* __restrict__ ps_w2,
                 const float* __restrict__ ps_b2, float* __restrict__ out)
{
    extern __shared__ __align__(16) char smx[];
    uint4* Bq = (uint4*)smx;                         // [kt][ntp][lane]
    float* fp = (float*)(smx + BF_BYTES);
    float* hI  = fp;                                 // [32][PAD]
    float* hJ  = hI + 32 * PAD;
    float* PI  = hJ + 32 * PAD;
    float* QI  = PI + 32 * PAD;
    float* PJ  = QI + 32 * PAD;
    float* QJ  = PJ + 32 * PAD;
    float* w2s = QJ + 32 * PAD;                      // [64]

    const int tid  = threadIdx.x;
    const int w    = tid >> 5;
    const int lane = tid & 31;
    const int gid  = lane >> 2;                      // 0..7
    const int tig  = lane & 3;                       // 0..3

    // B fragment table (uint4), tile-independent: load once.
    for (int e = tid; e < 8 * 4 * 32; e += 256) {
        int ktp = e >> 5, ln = e & 31;
        int kt = ktp >> 2, ntp = ktp & 3;
        int gd = ln >> 2, tg = ln & 3;
        int c0 = kt * 8 + tg;
        int n0 = (2 * ntp) * 8 + gd, n1 = (2 * ntp + 1) * 8 + gd;
        uint4 v;
        v.x = f2tf32(ps_w1[(128 + c0) * HIDD + n0]);
        v.y = f2tf32(ps_w1[(128 + c0 + 4) * HIDD + n0]);
        v.z = f2tf32(ps_w1[(128 + c0) * HIDD + n1]);
        v.w = f2tf32(ps_w1[(128 + c0 + 4) * HIDD + n1]);
        Bq[(size_t)ktp * 32 + ln] = v;
    }
    if (tid < 64) w2s[tid] = ps_w2[tid];
    const float b2v = ps_b2[0];

    #pragma unroll 1
    for (int t = blockIdx.x; t < TOTTILES; t += GRIDP) {
        const int b = t / NUPPER;
        int u = t - b * NUPPER, ti = 0;
        while (u >= NTILE - ti) { u -= NTILE - ti; ti++; }
        const int tj = ti + u;

        const int baseI = (b * NN + ti * 32) * HIDD;
        const int baseJ = (b * NN + tj * 32) * HIDD;

        __syncthreads();   // prior iteration's reads done (and Bq ready, iter 0)
        for (int e = tid; e < 32 * HIDD; e += 256) {
            int r = e >> 6, c = e & 63;
            hI[r * PAD + c] = g_h[baseI + e];
            hJ[r * PAD + c] = g_h[baseJ + e];
            PI[r * PAD + c] = g_P[baseI + e];
            QI[r * PAD + c] = g_Q[baseI + e];
            PJ[r * PAD + c] = g_P[baseJ + e];
            QJ[r * PAD + c] = g_Q[baseJ + e];
        }
        __syncthreads();

        float* ob = out + (size_t)b * NN * NN;

        #pragma unroll 1
        for (int it = 0; it < 4; it++) {
            const int i  = it * 8 + w;               // warp-uniform tile row
            const int iP = i * PAD;

            float acc[2][8][4];
            #pragma unroll
            for (int mt = 0; mt < 2; mt++)
                #pragma unroll
                for (int n = 0; n < 8; n++)
                    #pragma unroll
                    for (int x = 0; x < 4; x++) acc[mt][n][x] = 0.f;

            const int r0 = gid * PAD, r1 = (gid + 8) * PAD,
                      r2 = (gid + 16) * PAD, r3 = (gid + 24) * PAD;

            #pragma unroll
            for (int kt = 0; kt < 8; kt++) {
                const int c0 = kt * 8 + tig, c1 = c0 + 4;
                const float hi0 = hI[iP + c0], hi1 = hI[iP + c1];
                uint32_t A00 = f2tf32(fabsf(hi0 - hJ[r0 + c0]));
                uint32_t A01 = f2tf32(fabsf(hi0 - hJ[r1 + c0]));
                uint32_t A02 = f2tf32(fabsf(hi1 - hJ[r0 + c1]));
                uint32_t A03 = f2tf32(fabsf(hi1 - hJ[r1 + c1]));
                uint32_t A10 = f2tf32(fabsf(hi0 - hJ[r2 + c0]));
                uint32_t A11 = f2tf32(fabsf(hi0 - hJ[r3 + c0]));
                uint32_t A12 = f2tf32(fabsf(hi1 - hJ[r2 + c1]));
                uint32_t A13 = f2tf32(fabsf(hi1 - hJ[r3 + c1]));
                #pragma unroll
                for (int ntp = 0; ntp < 4; ntp++) {
                    uint4 bv = Bq[(size_t)(kt * 4 + ntp) * 32 + lane];
                    mma_tf32(acc[0][2 * ntp],     A00, A01, A02, A03, bv.x, bv.y);
                    mma_tf32(acc[1][2 * ntp],     A10, A11, A12, A13, bv.x, bv.y);
                    mma_tf32(acc[0][2 * ntp + 1], A00, A01, A02, A03, bv.z, bv.w);
                    mma_tf32(acc[1][2 * ntp + 1], A10, A11, A12, A13, bv.z, bv.w);
                }
            }

            // epilogue
            float sij[4], sji[4];
            #pragma unroll
            for (int rr = 0; rr < 4; rr++) { sij[rr] = 0.f; sji[rr] = 0.f; }

            #pragma unroll
            for (int nt = 0; nt < 8; nt++) {
                const int k0 = nt * 8 + tig * 2;
                const float2 piv = *(const float2*)&PI[iP + k0];
                const float2 qiv = *(const float2*)&QI[iP + k0];
                const float2 w2v = *(const float2*)&w2s[k0];
                #pragma unroll
                for (int rr = 0; rr < 4; rr++) {
                    const int row = gid + 8 * rr;
                    const float dk0 = acc[rr >> 1][nt][(rr & 1) * 2];
                    const float dk1 = acc[rr >> 1][nt][(rr & 1) * 2 + 1];
                    const float2 qjv = *(const float2*)&QJ[row * PAD + k0];
                    const float2 pjv = *(const float2*)&PJ[row * PAD + k0];
                    sij[rr] = fmaf(fmaxf(dk0 + piv.x + qjv.x, 0.f), w2v.x, sij[rr]);
                    sij[rr] = fmaf(fmaxf(dk1 + piv.y + qjv.y, 0.f), w2v.y, sij[rr]);
                    sji[rr] = fmaf(fmaxf(dk0 + pjv.x + qiv.x, 0.f), w2v.x, sji[rr]);
                    sji[rr] = fmaf(fmaxf(dk1 + pjv.y + qiv.y, 0.f), w2v.y, sji[rr]);
                }
            }

            // quad reduction; bias added once after
            #pragma unroll
            for (int rr = 0; rr < 4; rr++) {
                sij[rr] += __shfl_xor_sync(0xFFFFFFFF, sij[rr], 1);
                sij[rr] += __shfl_xor_sync(0xFFFFFFFF, sij[rr], 2);
                sji[rr] += __shfl_xor_sync(0xFFFFFFFF, sji[rr], 1);
                sji[rr] += __shfl_xor_sync(0xFFFFFFFF, sji[rr], 2);
            }

            const int j  = gid + 8 * tig;
            const int gi = ti * 32 + i, gj = tj * 32 + j;
            const float a_ij = sij[tig] + b2v;
            const float a_ji = sji[tig] + b2v;
            if (ti != tj || i < j) {
                float d = 0.5f * (tanhf(a_ij) + tanhf(a_ji));
                ob[(size_t)gi * NN + gj] = d;
                ob[(size_t)gj * NN + gi] = d;
            } else if (i == j) {
                ob[(size_t)gi * NN + gj] = 0.f;
            }
        }
    }
}

// ---------------------------------------------------------------------------
// Kernel 3: a = relu(a_static + lam*delta); row-normalize; write lam.
// ---------------------------------------------------------------------------
__global__ __launch_bounds__(256)
void finalize_kernel(const float* __restrict__ a_static,
                     const float* __restrict__ raw_lambda,
                     float* __restrict__ out, int out_size)
{
    const int row = blockIdx.x;
    const int b = row / NN, i = row % NN;
    const int tid = threadIdx.x;

    const float lam = 1.f / (1.f + expf(-raw_lambda[0]));
    float* orow = out + ((size_t)b * NN + i) * NN;
    const float* arow = a_static + (size_t)i * NN;

    float v[3];
    float s = 0.f;
    #pragma unroll
    for (int r = 0; r < 3; r++) {
        int j = tid + 256 * r;
        float a = fmaxf(fmaf(lam, orow[j], arow[j]), 0.f);
        v[r] = a;
        s += a;
    }

    __shared__ float red[256];
    red[tid] = s;
    __syncthreads();
    for (int off = 128; off > 0; off >>= 1) {
        if (tid < off) red[tid] += red[tid + off];
        __syncthreads();
    }
    float inv = 1.f / fmaxf(red[0], 1e-6f);
    #pragma unroll
    for (int r = 0; r < 3; r++) orow[tid + 256 * r] = v[r] * inv;

    if (row == 0 && tid == 0) {
        for (int idx = BB * NN * NN; idx < out_size; idx++) out[idx] = lam;
    }
}

// ---------------------------------------------------------------------------
extern "C" void kernel_launch(void* const* d_in, const int* in_sizes, int n_in,
                              void* d_out, int out_size)
{
    const float* x_hist   = (const float*)d_in[0];
    const float* x_mark   = (const float*)d_in[1];
    const float* a_static = (const float*)d_in[2];
    const float* te_w1 = (const float*)d_in[3];
    const float* te_b1 = (const float*)d_in[4];
    const float* te_w2 = (const float*)d_in[5];
    const float* te_b2 = (const float*)d_in[6];
    const float* me_w1 = (const float*)d_in[7];
    const float* me_b1 = (const float*)d_in[8];
    const float* me_w2 = (const float*)d_in[9];
    const float* me_b2 = (const float*)d_in[10];
    const float* nf_w  = (const float*)d_in[11];
    const float* nf_b  = (const float*)d_in[12];
    const float* ps_w1 = (const float*)d_in[13];
    const float* ps_b1 = (const float*)d_in[14];
    const float* ps_w2 = (const float*)d_in[15];
    const float* ps_b2 = (const float*)d_in[16];
    const float* raw_lambda = (const float*)d_in[17];
    float* out = (float*)d_out;

    static bool attr_set = false;
    if (!attr_set) {
        cudaFuncSetAttribute(pair_kernel,
                             cudaFuncAttributeMaxDynamicSharedMemorySize, SM_BYTES);
        attr_set = true;
    }

    node_kernel<<<BB * NN / 4, 64>>>(x_hist, x_mark, te_w1, te_b1, te_w2, te_b2,
                                     me_w1, me_b1, me_w2, me_b2, nf_w, nf_b,
                                     ps_w1, ps_b1);

    pair_kernel<<<GRIDP, 256, SM_BYTES>>>(ps_w1, ps_w2, ps_b2, out);

    finalize_kernel<<<BB * NN, 256>>>(a_static, raw_lambda, out, out_size);
}